// round 15
// baseline (speedup 1.0000x reference)
#include <cuda_runtime.h>
#include <math.h>
#include <stdint.h>

#define B_    64
#define NR_   16384
#define IC_   16
#define NC_   10
#define OC_   16
#define CO_   160
#define NS_   16          // K splits (grid.x)
#define KB_   1024        // K per CTA
#define KT_   32          // K per stage
#define NT_   (KB_/KT_)   // 32 stages
#define PITCH_A 20        // u32 per A smem row (16 pairs + 4 pad)
#define PITCH_W 40        // floats per W smem row (32 + 8 pad)
#define NPAIR   (NR_/2)   // 8192 bf16x2 pairs per (i,b)
#define STG_FLOATS (64*PITCH_A + 64*PITCH_A + CO_*PITCH_W)   // 8960
#define SMEM_GEMM  (3 * STG_FLOATS * 4)                      // 107520 B
#define NRB   40          // routing CTAs: 10 c x 4 b-quarters

// ---------------- device scratch ----------------
__device__ uint32_t g_xh[(size_t)IC_*B_*NPAIR];     // x hi bf16x2 [i][b][rpair]
__device__ uint32_t g_xl[(size_t)IC_*B_*NPAIR];     // x lo bf16x2
__device__ float g_uhatC[NC_*IC_*B_*OC_];           // uhat [c][i][b][o] (atomic accum)
__device__ float g_bijp[2][NC_*IC_*4];              // agreement partials [buf][c][i][bq]
__device__ float g_fcp[NC_*B_];                     // FC partials [c][b]
__device__ int g_bar;

// ---------------- helpers ----------------
__device__ __forceinline__ uint32_t smem_u32(const void* p) {
    uint32_t a;
    asm("{ .reg .u64 t; cvta.to.shared.u64 t, %1; cvt.u32.u64 %0, t; }" : "=r"(a) : "l"(p));
    return a;
}
__device__ __forceinline__ void cp16(uint32_t saddr, const void* g) {
    asm volatile("cp.async.cg.shared.global [%0], [%1], 16;" :: "r"(saddr), "l"(g));
}
#define CP_COMMIT() asm volatile("cp.async.commit_group;" ::: "memory")

// split packed pair (f0=k even, f1=k odd) into bf16x2 hi + bf16x2 lo
__device__ __forceinline__ void split_bf16x2(float f0, float f1, uint32_t& h, uint32_t& l) {
    asm("cvt.rn.satfinite.bf16x2.f32 %0, %1, %2;" : "=r"(h) : "f"(f1), "f"(f0));
    float g0 = __uint_as_float(h << 16);
    float g1 = __uint_as_float(h & 0xFFFF0000u);
    asm("cvt.rn.satfinite.bf16x2.f32 %0, %1, %2;" : "=r"(l) : "f"(f1 - g1), "f"(f0 - g0));
}
__device__ __forceinline__ void mma_bf16(float* d, const uint32_t* a,
                                         uint32_t b0, uint32_t b1) {
    asm("mma.sync.aligned.m16n8k16.row.col.f32.bf16.bf16.f32 "
        "{%0,%1,%2,%3},{%4,%5,%6,%7},{%8,%9},{%0,%1,%2,%3};"
        : "+f"(d[0]), "+f"(d[1]), "+f"(d[2]), "+f"(d[3])
        : "r"(a[0]), "r"(a[1]), "r"(a[2]), "r"(a[3]), "r"(b0), "r"(b1));
}
__device__ __forceinline__ void ldsm_x4(uint32_t* r, uint32_t saddr) {
    asm volatile("ldmatrix.sync.aligned.m8n8.x4.shared.b16 {%0,%1,%2,%3}, [%4];"
        : "=r"(r[0]), "=r"(r[1]), "=r"(r[2]), "=r"(r[3]) : "r"(saddr));
}

// ---------------- kernel 1: transpose+split x[b,r,i] -> xh/xl[i][b][rpair] ----
// also zeroes g_uhatC (GEMM atomic epilogue) and g_bar
#define TP 132   // smem row pitch (floats): 16B-aligned rows, phase2 LDS.128
__global__ __launch_bounds__(256) void transpose_kernel(const float* __restrict__ x) {
    __shared__ float s[4 * 16 * TP];            // [b4*16+i][r128]
    const int tid = threadIdx.x;
    const int r0 = blockIdx.x * 128, b0 = blockIdx.y * 4;
    const int bid = blockIdx.y * 128 + blockIdx.x;   // 0..2047
    if (bid == 0 && tid == 0) g_bar = 0;
    if (bid < 640) g_uhatC[bid * 256 + tid] = 0.f;   // 640*256 = 163840 floats
    #pragma unroll
    for (int it = 0; it < 8; it++) {
        int idx = it * 256 + tid;               // 2048 float4 over i
        int iq = idx & 3, r = (idx >> 2) & 127, b = idx >> 9;
        float4 v = *(const float4*)(x + ((size_t)(b0 + b) * NR_ + (r0 + r)) * IC_ + iq * 4);
        int base = (b * 16 + iq * 4) * TP + r;
        s[base] = v.x; s[base + TP] = v.y; s[base + 2 * TP] = v.z; s[base + 3 * TP] = v.w;
    }
    __syncthreads();
    #pragma unroll
    for (int it = 0; it < 4; it++) {
        int idx = it * 256 + tid;               // 1024 tasks: 8 r each
        int rg = idx & 15, i = (idx >> 4) & 15, b = idx >> 8;
        const float4* row = (const float4*)&s[(b * 16 + i) * TP + rg * 8];
        float4 f0 = row[0];                     // r = rg*8 .. +3
        float4 f1 = row[1];                     // r = rg*8+4 .. +7
        uint4 h, l;
        split_bf16x2(f0.x, f0.y, h.x, l.x);
        split_bf16x2(f0.z, f0.w, h.y, l.y);
        split_bf16x2(f1.x, f1.y, h.z, l.z);
        split_bf16x2(f1.z, f1.w, h.w, l.w);
        size_t po = (size_t)(i * B_ + b0 + b) * NPAIR + (r0 >> 1) + rg * 4;
        *(uint4*)(g_xh + po) = h;
        *(uint4*)(g_xl + po) = l;
    }
}

// ---------------- kernel 2: mma.sync bf16x3 K-split GEMM (atomic epilogue) ----
extern __shared__ float smf[];

__global__ __launch_bounds__(256, 2) void gemm_kernel(const float* __restrict__ W) {
    const int split = blockIdx.x, i = blockIdx.y;
    const int tid = threadIdx.x;
    const int wid = tid >> 5, lane = tid & 31;
    const int g = lane >> 2, c = lane & 3;
    const int mt = wid & 1;                     // m-tile (32 b rows)
    const int ng = wid >> 1;                    // n-group (40 co)
    const float* Wb = W + (size_t)i * CO_ * NR_ + split * KB_;
    const size_t ib = (size_t)i * B_;

    const int lm_row = mt * 32 + ((lane >> 3) & 1) * 8 + (lane & 7);
    const uint32_t lm_off = (uint32_t)(lm_row * PITCH_A + (lane >> 4) * 4) * 4;

    float acc[2][5][4];
    #pragma unroll
    for (int t = 0; t < 2; t++)
        #pragma unroll
        for (int nt = 0; nt < 5; nt++)
            #pragma unroll
            for (int q = 0; q < 4; q++) acc[t][nt][q] = 0.f;

    auto load_stage = [&](int t) {
        uint32_t sbase = smem_u32(smf + (t % 3) * STG_FLOATS);
        const int p0 = split * (KB_ / 2) + t * (KT_ / 2);   // pair offset
        #pragma unroll
        for (int j = 0; j < 7; j++) {           // 1792 chunks of 16B
            int idx = tid + j * 256;
            if (idx < 512) {
                int half = idx >> 8, r2 = idx & 255;
                int row = r2 >> 2, ch = r2 & 3;
                const uint32_t* src = (half ? g_xl : g_xh) + (ib + row) * NPAIR + p0 + ch * 4;
                cp16(sbase + (half * 1280 + row * PITCH_A + ch * 4) * 4, src);
            } else {
                int idx2 = idx - 512;
                int row = idx2 >> 3, ch = idx2 & 7;
                cp16(sbase + (2560 + row * PITCH_W + ch * 4) * 4,
                     Wb + (size_t)row * NR_ + t * KT_ + ch * 4);
            }
        }
        CP_COMMIT();
    };

    load_stage(0); load_stage(1);

    for (int t = 0; t < NT_; t++) {
        if (t + 1 < NT_) asm volatile("cp.async.wait_group 1;" ::: "memory");
        else             asm volatile("cp.async.wait_group 0;" ::: "memory");
        __syncthreads();                        // stage t visible; t-1 fully consumed
        if (t + 2 < NT_) load_stage(t + 2);     // overwrites buf (t-1)%3 — safe

        const uint32_t sb32 = smem_u32(smf + (t % 3) * STG_FLOATS);
        const float* ws = (const float*)((const uint32_t*)(smf + (t % 3) * STG_FLOATS) + 2560);
        #pragma unroll
        for (int kk = 0; kk < 2; kk++) {
            uint32_t ah[2][4], al[2][4];
            #pragma unroll
            for (int st2 = 0; st2 < 2; st2++) {
                uint32_t a0 = sb32 + lm_off + st2 * (16 * PITCH_A * 4) + kk * 32;
                ldsm_x4(ah[st2], a0);
                ldsm_x4(al[st2], a0 + 1280 * 4);
            }
            const int kc = kk * 16;
            #pragma unroll
            for (int nt = 0; nt < 5; nt++) {
                const int n = ng * 40 + nt * 8 + g;
                float2 q0 = *(const float2*)&ws[n * PITCH_W + kc + 2 * c];
                float2 q1 = *(const float2*)&ws[n * PITCH_W + kc + 2 * c + 8];
                uint32_t bh0, bl0, bh1, bl1;
                split_bf16x2(q0.x, q0.y, bh0, bl0);
                split_bf16x2(q1.x, q1.y, bh1, bl1);
                #pragma unroll
                for (int st2 = 0; st2 < 2; st2++) {
                    mma_bf16(acc[st2][nt], ah[st2], bh0, bh1);   // hi*hi
                    mma_bf16(acc[st2][nt], ah[st2], bl0, bl1);   // hi*lo
                    mma_bf16(acc[st2][nt], al[st2], bh0, bh1);   // lo*hi
                }
            }
        }
    }

    // epilogue: atomic accumulate into g_uhatC[c][i][b][o]
    #pragma unroll
    for (int st2 = 0; st2 < 2; st2++) {
        const int row = mt * 32 + st2 * 16 + g;
        #pragma unroll
        for (int nt = 0; nt < 5; nt++) {
            const int col = ng * 40 + nt * 8 + 2 * c;       // even, o and o+1 same c
            const int cc = col >> 4, o = col & 15;
            float* dst = g_uhatC + ((size_t)(cc * IC_ + i) * B_) * OC_ + o;
            atomicAdd(dst + (size_t)row * OC_,           acc[st2][nt][0]);
            atomicAdd(dst + (size_t)row * OC_ + 1,       acc[st2][nt][1]);
            atomicAdd(dst + (size_t)(row + 8) * OC_,     acc[st2][nt][2]);
            atomicAdd(dst + (size_t)(row + 8) * OC_ + 1, acc[st2][nt][3]);
        }
    }
}

// ---------------- kernel 3: routing + FC, 40 CTAs (10 c x 4 b-quarters) ----
__global__ __launch_bounds__(256) void routing_kernel(const float* __restrict__ fc_w,
                                                      const float* __restrict__ fc_b,
                                                      float* __restrict__ out) {
    const int bid = blockIdx.x;                 // 0..39
    const int c = bid >> 2, bq = bid & 3, b0 = bq * 16;
    const int tid = threadIdx.x;
    __shared__ float su[IC_ * 256];             // [i][bl*16+o]
    __shared__ float sv[256];
    __shared__ float sb[IC_];                   // private bij column (identical per c)
    __shared__ float sc[IC_];

    // load uhat slice: (c, all i, b0..b0+15, all o) — 16 KB
    #pragma unroll
    for (int j = 0; j < 4; j++) {
        int idx = tid + j * 256;                // 1024 float4
        int i = idx >> 6, rem = idx & 63;
        int bl = rem >> 2, oq = rem & 3;
        float4 v = *(const float4*)(g_uhatC + ((size_t)(c * IC_ + i) * B_ + b0 + bl) * OC_ + oq * 4);
        *(float4*)(su + i * 256 + bl * 16 + oq * 4) = v;
    }
    if (tid < IC_) sb[tid] = 0.f;
    __syncthreads();

    for (int it = 0; it < 3; it++) {
        if (tid < 32) {                         // softmax over i (width-16 shuffles)
            float bj = (tid < IC_) ? sb[tid] : -1e30f;
            float m = bj;
            #pragma unroll
            for (int off = 8; off > 0; off >>= 1)
                m = fmaxf(m, __shfl_xor_sync(0xFFFFFFFF, m, off, 16));
            float e = (tid < IC_) ? __expf(bj - m) : 0.f;
            float sum = e;
            #pragma unroll
            for (int off = 8; off > 0; off >>= 1)
                sum += __shfl_xor_sync(0xFFFFFFFF, sum, off, 16);
            if (tid < IC_) sc[tid] = e / sum;
        }
        __syncthreads();
        {                                       // s_j + squash, one element/thread
            float s = 0.f;
            #pragma unroll
            for (int i = 0; i < IC_; i++) s += sc[i] * su[i * 256 + tid];
            sv[tid] = s * fabsf(s) / (1.f + s * s);
        }
        __syncthreads();
        if (it < 2) {                           // agreement partial over this b-quarter
            int w = tid >> 5, lane = tid & 31;
            #pragma unroll
            for (int ii = w; ii < IC_; ii += 8) {
                float p = 0.f;
                #pragma unroll
                for (int j = 0; j < 8; j++)
                    p += su[ii * 256 + lane + j * 32] * sv[lane + j * 32];
                #pragma unroll
                for (int off = 16; off > 0; off >>= 1)
                    p += __shfl_xor_sync(0xFFFFFFFF, p, off);
                if (lane == 0) g_bijp[it & 1][(c * IC_ + ii) * 4 + bq] = p;
            }
            __threadfence();
            __syncthreads();
            if (tid == 0) {                     // 40-CTA spin barrier
                atomicAdd(&g_bar, 1);
                while (atomicAdd(&g_bar, 0) < NRB * (it + 1)) __nanosleep(32);
            }
            __syncthreads();
            __threadfence();
            if (tid < IC_) {                    // fold 4 partials in fixed order
                const float* pp = &g_bijp[it & 1][(c * IC_ + tid) * 4];
                sb[tid] += (pp[0] + pp[1] + pp[2] + pp[3]) * (1.f / B_);
            }
            __syncthreads();
        }
    }

    // write v slice + per-(c,b) FC partial (deterministic plain stores)
    {
        int bl = tid >> 4, o = tid & 15;
        float v = sv[tid];
        out[B_ + (b0 + bl) * CO_ + c * OC_ + o] = v;
        float p = v * fc_w[c * OC_ + o];
        #pragma unroll
        for (int off = 8; off > 0; off >>= 1)
            p += __shfl_xor_sync(0xFFFFFFFF, p, off, 16);
        if (o == 0) g_fcp[c * B_ + b0 + bl] = p;
    }
    __threadfence();
    __syncthreads();
    if (tid == 0) atomicAdd(&g_bar, 1);
    if (bid != 0) return;
    if (tid == 0) while (atomicAdd(&g_bar, 0) < NRB * 3) __nanosleep(32);
    __syncthreads();
    __threadfence();
    if (tid < B_) {
        float a = fc_b[0];
        #pragma unroll
        for (int cc = 0; cc < NC_; cc++) a += g_fcp[cc * B_ + tid];
        out[tid] = 1.f / (1.f + __expf(-a));
    }
}

// ---------------- launcher ----------------
extern "C" void kernel_launch(void* const* d_in, const int* in_sizes, int n_in,
                              void* d_out, int out_size) {
    const float* x    = (const float*)d_in[0];
    const float* W    = (const float*)d_in[1];
    const float* fc_w = (const float*)d_in[2];
    const float* fc_b = (const float*)d_in[3];
    float* out = (float*)d_out;

    static int attr_done = 0;
    if (!attr_done) {
        cudaFuncSetAttribute(gemm_kernel, cudaFuncAttributeMaxDynamicSharedMemorySize, SMEM_GEMM);
        attr_done = 1;
    }

    transpose_kernel<<<dim3(NR_ / 128, B_ / 4), 256>>>(x);
    gemm_kernel<<<dim3(NS_, IC_), 256, SMEM_GEMM>>>(W);
    routing_kernel<<<NRB, 256>>>(fc_w, fc_b, out);
}

// round 16
// speedup vs baseline: 1.0070x; 1.0070x over previous
#include <cuda_runtime.h>
#include <math.h>
#include <stdint.h>

#define B_    64
#define NR_   16384
#define IC_   16
#define NC_   10
#define OC_   16
#define CO_   160
#define NS_   16          // K splits (grid.x)
#define KB_   1024        // K per CTA
#define KT_   32          // K per stage
#define NT_   (KB_/KT_)   // 32 stages
#define PITCH_A 20        // u32 per A smem row (16 pairs + 4 pad)
#define PITCH_W 40        // floats per W smem row (32 + 8 pad)
#define NPAIR   (NR_/2)   // 8192 bf16x2 pairs per (i,b)
#define STG_FLOATS (64*PITCH_A + 64*PITCH_A + CO_*PITCH_W)   // 8960
#define SMEM_GEMM  (3 * STG_FLOATS * 4)                      // 107520 B
#define SMEM_ROUT  ((IC_*B_*OC_ + B_*OC_ + 48) * 4)

// ---------------- device scratch ----------------
__device__ uint32_t g_xh[(size_t)IC_*B_*NPAIR];     // x hi bf16x2 [i][b][rpair]
__device__ uint32_t g_xl[(size_t)IC_*B_*NPAIR];     // x lo bf16x2
__device__ float g_uhatC[NC_*IC_*B_*OC_];           // uhat [c][i][b][o] (atomic accum)
__device__ float g_fcp[NC_*B_];                     // per-c FC partials
__device__ int g_bar;

// ---------------- helpers ----------------
__device__ __forceinline__ uint32_t smem_u32(const void* p) {
    uint32_t a;
    asm("{ .reg .u64 t; cvta.to.shared.u64 t, %1; cvt.u32.u64 %0, t; }" : "=r"(a) : "l"(p));
    return a;
}
__device__ __forceinline__ void cp16(uint32_t saddr, const void* g) {
    asm volatile("cp.async.cg.shared.global [%0], [%1], 16;" :: "r"(saddr), "l"(g));
}
#define CP_COMMIT() asm volatile("cp.async.commit_group;" ::: "memory")

// split packed pair (f0=k even, f1=k odd) into bf16x2 hi + bf16x2 lo
__device__ __forceinline__ void split_bf16x2(float f0, float f1, uint32_t& h, uint32_t& l) {
    asm("cvt.rn.satfinite.bf16x2.f32 %0, %1, %2;" : "=r"(h) : "f"(f1), "f"(f0));
    float g0 = __uint_as_float(h << 16);
    float g1 = __uint_as_float(h & 0xFFFF0000u);
    asm("cvt.rn.satfinite.bf16x2.f32 %0, %1, %2;" : "=r"(l) : "f"(f1 - g1), "f"(f0 - g0));
}
__device__ __forceinline__ void mma_bf16(float* d, const uint32_t* a,
                                         uint32_t b0, uint32_t b1) {
    asm("mma.sync.aligned.m16n8k16.row.col.f32.bf16.bf16.f32 "
        "{%0,%1,%2,%3},{%4,%5,%6,%7},{%8,%9},{%0,%1,%2,%3};"
        : "+f"(d[0]), "+f"(d[1]), "+f"(d[2]), "+f"(d[3])
        : "r"(a[0]), "r"(a[1]), "r"(a[2]), "r"(a[3]), "r"(b0), "r"(b1));
}
__device__ __forceinline__ void ldsm_x4(uint32_t* r, uint32_t saddr) {
    asm volatile("ldmatrix.sync.aligned.m8n8.x4.shared.b16 {%0,%1,%2,%3}, [%4];"
        : "=r"(r[0]), "=r"(r[1]), "=r"(r[2]), "=r"(r[3]) : "r"(saddr));
}

// ---------------- kernel 1: transpose+split x[b,r,i] -> xh/xl[i][b][rpair] ----
// also zeroes g_uhatC (GEMM atomic epilogue) and g_bar
#define TP 132   // smem row pitch (floats): 16B-aligned rows, phase2 LDS.128
__global__ __launch_bounds__(256) void transpose_kernel(const float* __restrict__ x) {
    __shared__ float s[4 * 16 * TP];            // [b4*16+i][r128]
    const int tid = threadIdx.x;
    const int r0 = blockIdx.x * 128, b0 = blockIdx.y * 4;
    const int bid = blockIdx.y * 128 + blockIdx.x;   // 0..2047
    if (bid == 0 && tid == 0) g_bar = 0;
    if (bid < 640) g_uhatC[bid * 256 + tid] = 0.f;   // 640*256 = 163840 floats
    #pragma unroll
    for (int it = 0; it < 8; it++) {
        int idx = it * 256 + tid;               // 2048 float4 over i
        int iq = idx & 3, r = (idx >> 2) & 127, b = idx >> 9;
        float4 v = *(const float4*)(x + ((size_t)(b0 + b) * NR_ + (r0 + r)) * IC_ + iq * 4);
        int base = (b * 16 + iq * 4) * TP + r;
        s[base] = v.x; s[base + TP] = v.y; s[base + 2 * TP] = v.z; s[base + 3 * TP] = v.w;
    }
    __syncthreads();
    #pragma unroll
    for (int it = 0; it < 4; it++) {
        int idx = it * 256 + tid;               // 1024 tasks: 8 r each
        int rg = idx & 15, i = (idx >> 4) & 15, b = idx >> 8;
        const float4* row = (const float4*)&s[(b * 16 + i) * TP + rg * 8];
        float4 f0 = row[0];                     // r = rg*8 .. +3
        float4 f1 = row[1];                     // r = rg*8+4 .. +7
        uint4 h, l;
        split_bf16x2(f0.x, f0.y, h.x, l.x);
        split_bf16x2(f0.z, f0.w, h.y, l.y);
        split_bf16x2(f1.x, f1.y, h.z, l.z);
        split_bf16x2(f1.z, f1.w, h.w, l.w);
        size_t po = (size_t)(i * B_ + b0 + b) * NPAIR + (r0 >> 1) + rg * 4;
        *(uint4*)(g_xh + po) = h;
        *(uint4*)(g_xl + po) = l;
    }
}

// ---------------- kernel 2: mma.sync bf16x3 K-split GEMM (atomic epilogue) ----
extern __shared__ float smf[];

__global__ __launch_bounds__(256, 2) void gemm_kernel(const float* __restrict__ W) {
    const int split = blockIdx.x, i = blockIdx.y;
    const int tid = threadIdx.x;
    const int wid = tid >> 5, lane = tid & 31;
    const int g = lane >> 2, c = lane & 3;
    const int mt = wid & 1;                     // m-tile (32 b rows)
    const int ng = wid >> 1;                    // n-group (40 co)
    const float* Wb = W + (size_t)i * CO_ * NR_ + split * KB_;
    const size_t ib = (size_t)i * B_;

    const int lm_row = mt * 32 + ((lane >> 3) & 1) * 8 + (lane & 7);
    const uint32_t lm_off = (uint32_t)(lm_row * PITCH_A + (lane >> 4) * 4) * 4;

    float acc[2][5][4];
    #pragma unroll
    for (int t = 0; t < 2; t++)
        #pragma unroll
        for (int nt = 0; nt < 5; nt++)
            #pragma unroll
            for (int q = 0; q < 4; q++) acc[t][nt][q] = 0.f;

    auto load_stage = [&](int t) {
        uint32_t sbase = smem_u32(smf + (t % 3) * STG_FLOATS);
        const int p0 = split * (KB_ / 2) + t * (KT_ / 2);   // pair offset
        #pragma unroll
        for (int j = 0; j < 7; j++) {           // 1792 chunks of 16B
            int idx = tid + j * 256;
            if (idx < 512) {
                int half = idx >> 8, r2 = idx & 255;
                int row = r2 >> 2, ch = r2 & 3;
                const uint32_t* src = (half ? g_xl : g_xh) + (ib + row) * NPAIR + p0 + ch * 4;
                cp16(sbase + (half * 1280 + row * PITCH_A + ch * 4) * 4, src);
            } else {
                int idx2 = idx - 512;
                int row = idx2 >> 3, ch = idx2 & 7;
                cp16(sbase + (2560 + row * PITCH_W + ch * 4) * 4,
                     Wb + (size_t)row * NR_ + t * KT_ + ch * 4);
            }
        }
        CP_COMMIT();
    };

    load_stage(0); load_stage(1);

    for (int t = 0; t < NT_; t++) {
        if (t + 1 < NT_) asm volatile("cp.async.wait_group 1;" ::: "memory");
        else             asm volatile("cp.async.wait_group 0;" ::: "memory");
        __syncthreads();                        // stage t visible; t-1 fully consumed
        if (t + 2 < NT_) load_stage(t + 2);     // overwrites buf (t-1)%3 — safe

        const uint32_t sb32 = smem_u32(smf + (t % 3) * STG_FLOATS);
        const float* ws = (const float*)((const uint32_t*)(smf + (t % 3) * STG_FLOATS) + 2560);
        #pragma unroll
        for (int kk = 0; kk < 2; kk++) {
            uint32_t ah[2][4], al[2][4];
            #pragma unroll
            for (int st2 = 0; st2 < 2; st2++) {
                uint32_t a0 = sb32 + lm_off + st2 * (16 * PITCH_A * 4) + kk * 32;
                ldsm_x4(ah[st2], a0);
                ldsm_x4(al[st2], a0 + 1280 * 4);
            }
            const int kc = kk * 16;
            // nt pairs: term-major issue, same-acc distance 4 (covers HMMA RAW)
            #pragma unroll
            for (int np = 0; np < 2; np++) {
                const int n0 = (ng * 40 + (np * 2) * 8 + g) * PITCH_W + kc + 2 * c;
                const int n1 = n0 + 8 * PITCH_W;
                float2 p00 = *(const float2*)&ws[n0];
                float2 p01 = *(const float2*)&ws[n0 + 8];
                float2 p10 = *(const float2*)&ws[n1];
                float2 p11 = *(const float2*)&ws[n1 + 8];
                uint32_t bh00, bl00, bh01, bl01, bh10, bl10, bh11, bl11;
                split_bf16x2(p00.x, p00.y, bh00, bl00);
                split_bf16x2(p01.x, p01.y, bh01, bl01);
                split_bf16x2(p10.x, p10.y, bh10, bl10);
                split_bf16x2(p11.x, p11.y, bh11, bl11);
                float* a00 = acc[0][np * 2];  float* a10 = acc[1][np * 2];
                float* a01 = acc[0][np * 2 + 1]; float* a11 = acc[1][np * 2 + 1];
                // hh
                mma_bf16(a00, ah[0], bh00, bh01);
                mma_bf16(a10, ah[1], bh00, bh01);
                mma_bf16(a01, ah[0], bh10, bh11);
                mma_bf16(a11, ah[1], bh10, bh11);
                // hl
                mma_bf16(a00, ah[0], bl00, bl01);
                mma_bf16(a10, ah[1], bl00, bl01);
                mma_bf16(a01, ah[0], bl10, bl11);
                mma_bf16(a11, ah[1], bl10, bl11);
                // lh
                mma_bf16(a00, al[0], bh00, bh01);
                mma_bf16(a10, al[1], bh00, bh01);
                mma_bf16(a01, al[0], bh10, bh11);
                mma_bf16(a11, al[1], bh10, bh11);
            }
            {   // nt = 4 (single; distance 2)
                const int n = (ng * 40 + 4 * 8 + g) * PITCH_W + kc + 2 * c;
                float2 q0 = *(const float2*)&ws[n];
                float2 q1 = *(const float2*)&ws[n + 8];
                uint32_t bh0, bl0, bh1, bl1;
                split_bf16x2(q0.x, q0.y, bh0, bl0);
                split_bf16x2(q1.x, q1.y, bh1, bl1);
                mma_bf16(acc[0][4], ah[0], bh0, bh1);
                mma_bf16(acc[1][4], ah[1], bh0, bh1);
                mma_bf16(acc[0][4], ah[0], bl0, bl1);
                mma_bf16(acc[1][4], ah[1], bl0, bl1);
                mma_bf16(acc[0][4], al[0], bh0, bh1);
                mma_bf16(acc[1][4], al[1], bh0, bh1);
            }
        }
    }

    // epilogue: atomic accumulate into g_uhatC[c][i][b][o]
    #pragma unroll
    for (int st2 = 0; st2 < 2; st2++) {
        const int row = mt * 32 + st2 * 16 + g;
        #pragma unroll
        for (int nt = 0; nt < 5; nt++) {
            const int col = ng * 40 + nt * 8 + 2 * c;       // even, o and o+1 same c
            const int cc = col >> 4, o = col & 15;
            float* dst = g_uhatC + ((size_t)(cc * IC_ + i) * B_) * OC_ + o;
            atomicAdd(dst + (size_t)row * OC_,           acc[st2][nt][0]);
            atomicAdd(dst + (size_t)row * OC_ + 1,       acc[st2][nt][1]);
            atomicAdd(dst + (size_t)(row + 8) * OC_,     acc[st2][nt][2]);
            atomicAdd(dst + (size_t)(row + 8) * OC_ + 1, acc[st2][nt][3]);
        }
    }
}

// ---------------- kernel 3: routing + FC head (one CTA per column c) -------
extern __shared__ float rsm[];
__global__ __launch_bounds__(1024) void routing_kernel(const float* __restrict__ fc_w,
                                                       const float* __restrict__ fc_b,
                                                       float* __restrict__ out) {
    const int c = blockIdx.x;
    const int tid = threadIdx.x;
    float* su = rsm;                       // [i][b*o] 16x1024
    float* sv = rsm + IC_ * 1024;          // [b*o] 1024
    float* sb = sv + 1024;                 // bij col (16)
    float* sc = sb + IC_;                  // softmax  (16)

    // load uhat slice for column c: contiguous 64 KB
    const float4* src = (const float4*)(g_uhatC + c * IC_ * 1024);
    #pragma unroll
    for (int j = 0; j < 4; j++)
        ((float4*)su)[tid + j * 1024] = src[tid + j * 1024];
    if (tid < IC_) sb[tid] = 0.f;
    __syncthreads();

    for (int it = 0; it < 3; it++) {
        if (tid < 32) {                    // softmax over i: lane j owns i=j (j<16)
            float bj = (tid < IC_) ? sb[tid] : -1e30f;
            float m = bj;
            #pragma unroll
            for (int off = 8; off > 0; off >>= 1)
                m = fmaxf(m, __shfl_xor_sync(0xFFFFFFFF, m, off, 16));
            float e = (tid < IC_) ? __expf(bj - m) : 0.f;
            float sum = e;
            #pragma unroll
            for (int off = 8; off > 0; off >>= 1)
                sum += __shfl_xor_sync(0xFFFFFFFF, sum, off, 16);
            if (tid < IC_) sc[tid] = e / sum;
        }
        __syncthreads();
        {                                  // s_j + squash, one element/thread
            float s = 0.f;
            #pragma unroll
            for (int i = 0; i < IC_; i++) s += sc[i] * su[i * 1024 + tid];
            sv[tid] = s * fabsf(s) / (1.f + s * s);
        }
        __syncthreads();
        if (it < 2) {                      // agreement: warp w handles i=w (w<16)
            int i = tid >> 5, lane = tid & 31;
            if (i < IC_) {
                float p = 0.f;
                #pragma unroll
                for (int j = 0; j < 32; j++) {
                    int e = lane + j * 32;
                    p += su[i * 1024 + e] * sv[e];
                }
                #pragma unroll
                for (int off = 16; off > 0; off >>= 1)
                    p += __shfl_xor_sync(0xFFFFFFFF, p, off);
                if (lane == 0) sb[i] += p * (1.f / B_);
            }
            __syncthreads();
        }
    }
    // write v slice + per-c FC partial
    int b = tid >> 4, o = tid & 15;
    float v = sv[tid];
    out[B_ + b * CO_ + c * OC_ + o] = v;
    float p = v * fc_w[c * OC_ + o];
    #pragma unroll
    for (int off = 8; off > 0; off >>= 1)
        p += __shfl_xor_sync(0xFFFFFFFF, p, off, 16);
    if (o == 0) g_fcp[c * B_ + b] = p;

    // FC head: CTA 0 waits for all 10 CTAs (all co-resident at grid=10)
    __threadfence();
    __syncthreads();
    if (tid == 0) atomicAdd(&g_bar, 1);
    if (c != 0) return;
    if (tid == 0) while (atomicAdd(&g_bar, 0) < NC_) __nanosleep(64);
    __syncthreads();
    __threadfence();
    if (tid < B_) {
        float a = fc_b[0];
        #pragma unroll
        for (int cc = 0; cc < NC_; cc++) a += g_fcp[cc * B_ + tid];
        out[tid] = 1.f / (1.f + __expf(-a));
    }
}

// ---------------- launcher ----------------
extern "C" void kernel_launch(void* const* d_in, const int* in_sizes, int n_in,
                              void* d_out, int out_size) {
    const float* x    = (const float*)d_in[0];
    const float* W    = (const float*)d_in[1];
    const float* fc_w = (const float*)d_in[2];
    const float* fc_b = (const float*)d_in[3];
    float* out = (float*)d_out;

    static int attr_done = 0;
    if (!attr_done) {
        cudaFuncSetAttribute(gemm_kernel, cudaFuncAttributeMaxDynamicSharedMemorySize, SMEM_GEMM);
        cudaFuncSetAttribute(routing_kernel, cudaFuncAttributeMaxDynamicSharedMemorySize, SMEM_ROUT);
        attr_done = 1;
    }

    transpose_kernel<<<dim3(NR_ / 128, B_ / 4), 256>>>(x);
    gemm_kernel<<<dim3(NS_, IC_), 256, SMEM_GEMM>>>(W);
    routing_kernel<<<NC_, 1024, SMEM_ROUT>>>(fc_w, fc_b, out);
}